// round 7
// baseline (speedup 1.0000x reference)
#include <cuda_runtime.h>
#include <math.h>

#define B_    32
#define NCH   1024
#define NPTS  4096
#define QS    16         // point splits
#define QP    256        // points per block
#define SEGSZ 32
#define NSEG  8
#define SSTR  36         // 32 data + 4 skew floats
#define ROWF  (NSEG * SSTR)   // 288 floats per coord row

// packed argmax partials: [q][b][c] -> (ordf(max)<<32) | (4095 - idx)
__device__ unsigned long long g_part[QS * B_ * NCH];

typedef unsigned long long ull;

__device__ __forceinline__ ull mul2_(ull a, ull b) {
    ull r; asm("mul.rn.f32x2 %0,%1,%2;" : "=l"(r) : "l"(a), "l"(b)); return r;
}
__device__ __forceinline__ ull fma2_(ull a, ull b, ull c) {
    ull r; asm("fma.rn.f32x2 %0,%1,%2,%3;" : "=l"(r) : "l"(a), "l"(b), "l"(c)); return r;
}
__device__ __forceinline__ void upk2(ull v, float& lo, float& hi) {
    asm("mov.b64 {%0,%1}, %2;" : "=f"(lo), "=f"(hi) : "l"(v));
}
__device__ __forceinline__ ull pkw(float w) {
    ull r; asm("mov.b64 %0, {%1,%1};" : "=l"(r) : "f"(w)); return r;
}
__device__ __forceinline__ unsigned int ordf(float f) {
    unsigned int u = __float_as_uint(f);
    return (u & 0x80000000u) ? ~u : (u | 0x80000000u);
}

// ---------------------------------------------------------------------------
// Kernel 1: partial argmax, 4 channels per thread, single wave (occ 4).
// grid = 512 (32 b x 16 q), 256 threads. Also writes the x passthrough.
// ---------------------------------------------------------------------------
__global__ void __launch_bounds__(256, 4) argmax_kernel(
    const float* __restrict__ x, const float* __restrict__ W,
    float* __restrict__ out_x)
{
    __shared__ __align__(16) float sx[3 * ROWF];

    const int b = blockIdx.x >> 4;
    const int q = blockIdx.x & 15;

    const float* src = x     + (size_t)b * 3 * NPTS + q * QP;
    float*       dst = out_x + (size_t)b * 3 * NPTS + q * QP;
    {
        int i = threadIdx.x;
        if (i < 192) {                       // 3 rows x 64 float4
            int row = i >> 6;
            int li  = (i & 63) << 2;
            float4 v = *(const float4*)(src + row * NPTS + li);
            *(float4*)(sx + row * ROWF + (li >> 5) * SSTR + (li & 31)) = v;
            *(float4*)(dst + row * NPTS + li) = v;   // fold x passthrough
        }
    }
    __syncthreads();

    const int t = threadIdx.x;
    ull W0[4], W1[4], W2[4];
    #pragma unroll
    for (int s = 0; s < 4; ++s) {
        int c = s * 256 + t;
        W0[s] = pkw(W[c * 3 + 0]);
        W1[s] = pkw(W[c * 3 + 1]);
        W2[s] = pkw(W[c * 3 + 2]);
    }

    float gmax[4]; int gseg[4];
    #pragma unroll
    for (int s = 0; s < 4; ++s) { gmax[s] = -INFINITY; gseg[s] = 0; }

    #pragma unroll 1
    for (int sg = 0; sg < NSEG; ++sg) {
        const float* a0 = sx + sg * SSTR;
        const float* a1 = a0 + ROWF;
        const float* a2 = a0 + 2 * ROWF;

        float m[4][2];
        #pragma unroll
        for (int c = 0; c < 4; ++c) m[c][0] = m[c][1] = -INFINITY;

        #pragma unroll
        for (int i = 0; i < SEGSZ; i += 4) {
            ulonglong2 xx = *(const ulonglong2*)(a0 + i);
            ulonglong2 yy = *(const ulonglong2*)(a1 + i);
            ulonglong2 zz = *(const ulonglong2*)(a2 + i);
            #pragma unroll
            for (int c = 0; c < 4; ++c) {
                ull vlo = fma2_(W2[c], zz.x, fma2_(W1[c], yy.x, mul2_(W0[c], xx.x)));
                ull vhi = fma2_(W2[c], zz.y, fma2_(W1[c], yy.y, mul2_(W0[c], xx.y)));
                float f0, f1, f2, f3;
                upk2(vlo, f0, f1); upk2(vhi, f2, f3);
                float t0 = fmaxf(f0, f2);
                float t1 = fmaxf(f1, f3);
                m[c][0] = fmaxf(m[c][0], t0);
                m[c][1] = fmaxf(m[c][1], t1);
            }
        }
        #pragma unroll
        for (int c = 0; c < 4; ++c) {
            float sm = fmaxf(m[c][0], m[c][1]);
            if (sm > gmax[c]) { gmax[c] = sm; gseg[c] = sg; }  // strict >: earliest seg
        }
    }

    // pass 2: vectorized rescan of winning segment; descending-index SEL chain
    // with bitwise-identical packed recompute -> exact first-index semantics.
    #pragma unroll
    for (int c = 0; c < 4; ++c) {
        const float gm = gmax[c];
        const float* a0 = sx + gseg[c] * SSTR;
        const float* a1 = a0 + ROWF;
        const float* a2 = a0 + 2 * ROWF;
        int fi = 0;
        #pragma unroll
        for (int k = SEGSZ - 4; k >= 0; k -= 4) {
            ulonglong2 xx = *(const ulonglong2*)(a0 + k);
            ulonglong2 yy = *(const ulonglong2*)(a1 + k);
            ulonglong2 zz = *(const ulonglong2*)(a2 + k);
            ull vlo = fma2_(W2[c], zz.x, fma2_(W1[c], yy.x, mul2_(W0[c], xx.x)));
            ull vhi = fma2_(W2[c], zz.y, fma2_(W1[c], yy.y, mul2_(W0[c], xx.y)));
            float f0, f1, f2, f3;
            upk2(vlo, f0, f1); upk2(vhi, f2, f3);
            fi = (f3 == gm) ? k + 3 : fi;
            fi = (f2 == gm) ? k + 2 : fi;
            fi = (f1 == gm) ? k + 1 : fi;
            fi = (f0 == gm) ? k     : fi;
        }
        int gidx = q * QP + gseg[c] * SEGSZ + fi;
        g_part[((size_t)q * B_ + b) * NCH + c * 256 + t] =
            ((ull)ordf(gm) << 32) | (ull)(unsigned)(4095 - gidx);
    }
}

// ---------------------------------------------------------------------------
// Kernel 2: merge 16 partials, counts, entropy, parallel stable counting sort.
// grid = 32, 1024 threads. Chunk = 128 pts -> 32 chunks, u16 hist (prefix can
// reach 4096 -> u16 REQUIRED; u8 overflowed in R6).
// ---------------------------------------------------------------------------
__global__ void __launch_bounds__(1024) sort_entropy_kernel(
    float* __restrict__ out_counts,
    float* __restrict__ out_imp2,
    float* __restrict__ out_ent)
{
    extern __shared__ __align__(16) char smem_raw[];
    int*            scnt   = (int*)smem_raw;                       // [0, 16384)
    int*            gstart = (int*)(smem_raw + 16384);             // 1025 ints -> 20484
    unsigned short* chh    = (unsigned short*)(smem_raw + 20488);  // 1025*33 u16 = 67650 B
    unsigned char*  lrk    = (unsigned char*)(smem_raw + 88140);   // 4096 u8
    __shared__ float red[32];
    __shared__ int   ired[32];

    const int b    = blockIdx.x;
    const int t    = threadIdx.x;
    const int lane = t & 31;
    const int wid  = t >> 5;

    // B0: prefetch the 16 partials (LDGs issue before zeroing hides latency)
    ull k[QS];
    #pragma unroll
    for (int qq = 0; qq < QS; ++qq)
        k[qq] = g_part[((size_t)qq * B_ + b) * NCH + t];

    // A: zero
    #pragma unroll
    for (int i = t; i < NPTS; i += 1024) scnt[i] = 0;
    for (int i = t; i < 16913; i += 1024) ((unsigned*)chh)[i] = 0;

    // B1: merge partials (register-only, overlaps other warps' zeroing)
    ull kk = k[0];
    #pragma unroll
    for (int qq = 1; qq < QS; ++qq) kk = kk > k[qq] ? kk : k[qq];
    __syncthreads();
    atomicAdd(&scnt[4095 - (int)(unsigned)kk], 1);
    __syncthreads();

    // C: write counts (float4) + entropy partial (sum analytically = 1024+4096e-6)
    const float inv_s = 1.0f / (1024.0f + 4096.0f * 1e-6f);
    float part2;
    {
        int4 cv = ((const int4*)scnt)[t];
        float4 cf = make_float4((float)cv.x, (float)cv.y, (float)cv.z, (float)cv.w);
        ((float4*)(out_counts + (size_t)b * NPTS))[t] = cf;
        float p0 = (cf.x + 1e-6f) * inv_s, p1 = (cf.y + 1e-6f) * inv_s;
        float p2 = (cf.z + 1e-6f) * inv_s, p3 = (cf.w + 1e-6f) * inv_s;
        part2 = p0 * __log2f(p0) + p1 * __log2f(p1)
              + p2 * __log2f(p2) + p3 * __log2f(p3);
    }

    // D: per-chunk stable local ranks (32 warps, chunk = 128 pts, 4 rounds)
    {
        #pragma unroll 1
        for (int r = 0; r < 4; ++r) {
            int n = (wid << 7) + (r << 5) + lane;
            int v = scnt[n];
            unsigned peers = __match_any_sync(0xffffffffu, v);
            int lr = __popc(peers & ((1u << lane) - 1u));
            int base = chh[v * 33 + wid];
            lrk[n] = (unsigned char)(base + lr);     // local rank < 128 fits u8
            if (lane == (__ffs(peers) - 1))
                chh[v * 33 + wid] = (unsigned short)(base + __popc(peers));
            __syncwarp();
        }
    }
    __syncthreads();

    // E: entropy reduction
    #pragma unroll
    for (int o = 16; o; o >>= 1) part2 += __shfl_down_sync(0xffffffffu, part2, o);
    if (lane == 0) red[wid] = part2;
    __syncthreads();
    if (wid == 0) {
        float v = red[lane];
        #pragma unroll
        for (int o = 16; o; o >>= 1) v += __shfl_down_sync(0xffffffffu, v, o);
        if (lane == 0) out_ent[b] = -v * (1.0f / 12.0f);   // log2(4096)=12
    }

    // F: per-value prefix across 32 chunks (thread t <-> value t); totals in reg
    int tot;
    {
        int run = 0;
        #pragma unroll
        for (int w = 0; w < 32; ++w) {
            int cc = chh[t * 33 + w];
            chh[t * 33 + w] = (unsigned short)run;   // prefix up to 4096: u16 ok
            run += cc;
        }
        tot = run;
        if (t == 0) {    // value 1024 (all channels same point)
            int r2 = 0;
            #pragma unroll
            for (int w = 0; w < 32; ++w) {
                int cc = chh[1024 * 33 + w];
                chh[1024 * 33 + w] = (unsigned short)r2;
                r2 += cc;
            }
            gstart[1024] = 4096 - r2;
        }
    }

    // G: parallel exclusive scan of value totals (0..1023)
    int incl = tot;
    #pragma unroll
    for (int o = 1; o < 32; o <<= 1) {
        int u = __shfl_up_sync(0xffffffffu, incl, o);
        if (lane >= o) incl += u;
    }
    if (lane == 31) ired[wid] = incl;
    __syncthreads();
    if (wid == 0) {
        int v = ired[lane];
        int sc = v;
        #pragma unroll
        for (int o = 1; o < 32; o <<= 1) {
            int u = __shfl_up_sync(0xffffffffu, sc, o);
            if (lane >= o) sc += u;
        }
        ired[lane] = sc - v;    // exclusive warp bases
    }
    __syncthreads();
    gstart[t] = incl - tot + ired[wid];
    __syncthreads();

    // H: scatter final ranks
    #pragma unroll
    for (int n = t; n < NPTS; n += 1024) {
        int v = scnt[n];
        int rank = gstart[v] + (int)chh[v * 33 + (n >> 7)] + (int)lrk[n];
        out_imp2[(size_t)b * NPTS + rank] = (float)n;
    }
}

// ---------------------------------------------------------------------------
extern "C" void kernel_launch(void* const* d_in, const int* in_sizes, int n_in,
                              void* d_out, int out_size)
{
    const float* x = (const float*)d_in[0];   // [32, 3, 4096]
    const float* W = (const float*)d_in[1];   // [1024, 3]
    float* out = (float*)d_out;

    float* out_x      = out;
    float* out_counts = out + B_ * 3 * NPTS;
    float* out_imp2   = out_counts + B_ * NPTS;
    float* out_ent    = out_imp2 + B_ * NPTS;

    const int SORT_SMEM = 92544;   // scnt + gstart + chh(u16) + lrk
    cudaFuncSetAttribute(sort_entropy_kernel,
                         cudaFuncAttributeMaxDynamicSharedMemorySize, SORT_SMEM);

    argmax_kernel<<<B_ * QS, 256>>>(x, W, out_x);
    sort_entropy_kernel<<<B_, 1024, SORT_SMEM>>>(out_counts, out_imp2, out_ent);
}